// round 1
// baseline (speedup 1.0000x reference)
#include <cuda_runtime.h>

#define NDRUG 846
#define EDIM  64
#define SNEI  1024
#define RLEN  100

// ---- scratch (__device__ globals: no allocation allowed) ----
__device__ float g_b2s[SNEI];           // row-sums of b2
__device__ float g_we[NDRUG * EDIM];    // weighted entity embedding per drug

// ------------------------------------------------------------------
// kernel 0: b2sum[s] = sum_f b2[s,f]
// ------------------------------------------------------------------
__global__ void k_b2sum(const float* __restrict__ b2) {
    int wid = threadIdx.x >> 5, lane = threadIdx.x & 31;
    int s = blockIdx.x * 8 + wid;
    if (s >= SNEI) return;
    float2 v = *reinterpret_cast<const float2*>(b2 + s * 64 + lane * 2);
    float acc = v.x + v.y;
    #pragma unroll
    for (int o = 16; o; o >>= 1) acc += __shfl_xor_sync(0xffffffffu, acc, o);
    if (lane == 0) g_b2s[s] = acc;
}

// ------------------------------------------------------------------
// kernel 1: one CTA per drug.
//   A[r,e]   = drug_emb[e] * rela_table[r,e]          (smem, 100x64)
//   M[r,f]   = sum_e A[r,e] * W1[n,e,f]               (smem GEMM)
//   w2sum[f] = sum_f' W2[n,f,f']
//   score[s] = dot(relu(M[r(s),:] + b1[s,:]), w2sum) + b2sum[s]
//   attn     = softmax_s(score)
//   we[n,f]  = sum_s attn[s] * ent_table[tail(s), f]  (thresholded gather)
// ------------------------------------------------------------------
// smem layout (floats):
//   As     [0      , 6400 )
//   W1s    [6400   , 10496)
//   Ms     [10496  , 16896)
//   scores [16896  , 17920)
//   w2sum  [17920  , 17984)
//   psum   [17984  , 18496)   (256 used for w2sum partials, 512 for gather)
//   red    [18496  , 18528)
#define K1_SMEM_FLOATS 18528
#define K1_SMEM_BYTES  (K1_SMEM_FLOATS * 4)

__global__ void __launch_bounds__(256, 3)
k_drug(const int*   __restrict__ dn,
       const int*   __restrict__ adjt,
       const int*   __restrict__ adjr,
       const float* __restrict__ drug_table,
       const float* __restrict__ rela_table,
       const float* __restrict__ ent_table,
       const float* __restrict__ W1,
       const float* __restrict__ b1,
       const float* __restrict__ W2) {
    extern __shared__ float sm[];
    float* As     = sm;
    float* W1s    = sm + 6400;
    float* Ms     = sm + 10496;
    float* scores = sm + 16896;
    float* w2sum  = sm + 17920;
    float* psum   = sm + 17984;
    float* red    = sm + 18496;

    const int n    = blockIdx.x;
    const int tid  = threadIdx.x;
    const int wid  = tid >> 5;
    const int lane = tid & 31;

    const int dbase = dn[n] * 64;

    // A = drug_emb (broadcast) * rela_table   (coalesced over i)
    for (int i = tid; i < RLEN * 64; i += 256)
        As[i] = drug_table[dbase + (i & 63)] * rela_table[i];

    // W1 -> smem
    {
        const float4* src = reinterpret_cast<const float4*>(W1 + (size_t)n * 4096);
        float4* dst = reinterpret_cast<float4*>(W1s);
        for (int i = tid; i < 1024; i += 256) dst[i] = src[i];
    }

    // w2sum partials: thread (f = tid>>2, quarter q = tid&3) sums 16 contiguous
    {
        int f = tid >> 2, q = tid & 3;
        const float4* p = reinterpret_cast<const float4*>(W2 + (size_t)n * 4096 + f * 64 + q * 16);
        float4 a = p[0], b = p[1], c = p[2], d = p[3];
        psum[tid] = (a.x + a.y + a.z + a.w) + (b.x + b.y + b.z + b.w)
                  + (c.x + c.y + c.z + c.w) + (d.x + d.y + d.z + d.w);
    }
    __syncthreads();
    if (tid < 64)
        w2sum[tid] = psum[tid * 4] + psum[tid * 4 + 1] + psum[tid * 4 + 2] + psum[tid * 4 + 3];
    __syncthreads();

    // ---- GEMM: M[r][f] = sum_e A[r][e] * W1[e][f]; lane owns f = {2*lane, 2*lane+1}
    const float2* W1f2 = reinterpret_cast<const float2*>(W1s);
    for (int r0 = wid * 4; r0 <= 96; r0 += 32) {
        float2 acc[4];
        #pragma unroll
        for (int j = 0; j < 4; j++) acc[j] = make_float2(0.f, 0.f);
        #pragma unroll 4
        for (int e0 = 0; e0 < 64; e0 += 4) {
            float a[4][4];
            #pragma unroll
            for (int j = 0; j < 4; j++)
                *reinterpret_cast<float4*>(a[j]) =
                    *reinterpret_cast<const float4*>(&As[(r0 + j) * 64 + e0]);
            #pragma unroll
            for (int ee = 0; ee < 4; ee++) {
                float2 w = W1f2[(e0 + ee) * 32 + lane];
                #pragma unroll
                for (int j = 0; j < 4; j++) {
                    acc[j].x = fmaf(a[j][ee], w.x, acc[j].x);
                    acc[j].y = fmaf(a[j][ee], w.y, acc[j].y);
                }
            }
        }
        #pragma unroll
        for (int j = 0; j < 4; j++)
            reinterpret_cast<float2*>(Ms)[(r0 + j) * 32 + lane] = acc[j];
    }
    __syncthreads();

    // ---- scores: one warp per s
    const float2 w2v = *reinterpret_cast<const float2*>(&w2sum[lane * 2]);
    const float2* b1f2 = reinterpret_cast<const float2*>(b1);
    const float2* Mf2  = reinterpret_cast<const float2*>(Ms);
    const int* adjr_n = adjr + (size_t)n * SNEI;
    for (int s = wid; s < SNEI; s += 8) {
        int r = adjr_n[s];
        float2 m = Mf2[r * 32 + lane];
        float2 b = b1f2[s * 32 + lane];
        float h0 = fmaxf(m.x + b.x, 0.f);
        float h1 = fmaxf(m.y + b.y, 0.f);
        float v = fmaf(h0, w2v.x, h1 * w2v.y);
        #pragma unroll
        for (int o = 16; o; o >>= 1) v += __shfl_xor_sync(0xffffffffu, v, o);
        if (lane == 0) scores[s] = v + g_b2s[s];
    }
    __syncthreads();

    // ---- softmax over 1024 scores (in smem)
    float lm = -1e30f;
    for (int i = tid; i < SNEI; i += 256) lm = fmaxf(lm, scores[i]);
    #pragma unroll
    for (int o = 16; o; o >>= 1) lm = fmaxf(lm, __shfl_xor_sync(0xffffffffu, lm, o));
    if (lane == 0) red[wid] = lm;
    __syncthreads();
    if (tid == 0) {
        float m = red[0];
        #pragma unroll
        for (int i = 1; i < 8; i++) m = fmaxf(m, red[i]);
        red[8] = m;
    }
    __syncthreads();
    const float mx = red[8];
    float ls = 0.f;
    for (int i = tid; i < SNEI; i += 256) {
        float w = __expf(scores[i] - mx);
        scores[i] = w;
        ls += w;
    }
    #pragma unroll
    for (int o = 16; o; o >>= 1) ls += __shfl_xor_sync(0xffffffffu, ls, o);
    if (lane == 0) red[16 + wid] = ls;
    __syncthreads();
    if (tid == 0) {
        float t = 0.f;
        #pragma unroll
        for (int i = 0; i < 8; i++) t += red[16 + i];
        red[9] = 1.f / t;
    }
    __syncthreads();
    const float inv = red[9];

    // ---- weighted entity gather (skip negligible attention weights)
    float2 acc = make_float2(0.f, 0.f);
    const float2* entf2 = reinterpret_cast<const float2*>(ent_table);
    const int* adjt_n = adjt + (size_t)n * SNEI;
    for (int s = wid; s < SNEI; s += 8) {
        float w = scores[s] * inv;           // uniform across warp
        if (w > 1e-8f) {
            int t = adjt_n[s];
            float2 ev = entf2[(size_t)t * 32 + lane];
            acc.x = fmaf(w, ev.x, acc.x);
            acc.y = fmaf(w, ev.y, acc.y);
        }
    }
    reinterpret_cast<float2*>(psum)[wid * 32 + lane] = acc;
    __syncthreads();
    if (tid < 64) {
        float v = 0.f;
        #pragma unroll
        for (int w = 0; w < 8; w++) v += psum[w * 64 + tid];
        g_we[n * 64 + tid] = v;
    }
}

// ------------------------------------------------------------------
// kernel 2: one CTA per output feature f.
//   x[n,f] = relu([we[n,:], drug_emb[n,:]] . lin_W[f,:] + lin_b[f])
//   out[n,f] = (x - mean_n) * rsqrt(var_n + eps) * gamma[f] + beta[f]
// ------------------------------------------------------------------
__global__ void __launch_bounds__(256)
k_final(const int*   __restrict__ dn,
        const float* __restrict__ drug_table,
        const float* __restrict__ lin_W,
        const float* __restrict__ lin_b,
        const float* __restrict__ gamma,
        const float* __restrict__ beta,
        float* __restrict__ out) {
    __shared__ float lw[128];
    __shared__ float xcol[NDRUG];
    __shared__ float redbuf[16];
    __shared__ float s_mean, s_scale;

    const int f = blockIdx.x;
    const int tid = threadIdx.x, wid = tid >> 5, lane = tid & 31;

    if (tid < 128) lw[tid] = lin_W[f * 128 + tid];
    __syncthreads();

    const float lb = lin_b[f];
    float lsum = 0.f, lsq = 0.f;
    for (int n = wid; n < NDRUG; n += 8) {
        const float* we = g_we + n * 64;
        int db = dn[n] * 64;
        float v = we[lane] * lw[lane]
                + we[lane + 32] * lw[lane + 32]
                + drug_table[db + lane] * lw[64 + lane]
                + drug_table[db + lane + 32] * lw[96 + lane];
        #pragma unroll
        for (int o = 16; o; o >>= 1) v += __shfl_xor_sync(0xffffffffu, v, o);
        float x = fmaxf(v + lb, 0.f);
        if (lane == 0) { xcol[n] = x; lsum += x; lsq += x * x; }
    }
    if (lane == 0) { redbuf[wid] = lsum; redbuf[8 + wid] = lsq; }
    __syncthreads();
    if (tid == 0) {
        float sm = 0.f, sq = 0.f;
        #pragma unroll
        for (int i = 0; i < 8; i++) { sm += redbuf[i]; sq += redbuf[8 + i]; }
        float mean = sm / (float)NDRUG;
        float var  = sq / (float)NDRUG - mean * mean;
        s_mean  = mean;
        s_scale = rsqrtf(var + 1e-5f) * gamma[f];
    }
    __syncthreads();
    const float mean = s_mean, scal = s_scale, bet = beta[f];
    for (int n = tid; n < NDRUG; n += 256)
        out[n * 64 + f] = (xcol[n] - mean) * scal + bet;
}

// ------------------------------------------------------------------
extern "C" void kernel_launch(void* const* d_in, const int* in_sizes, int n_in,
                              void* d_out, int out_size) {
    const int*   dn         = (const int*)  d_in[0];
    const int*   adjt       = (const int*)  d_in[1];
    const int*   adjr       = (const int*)  d_in[2];
    const float* drug_table = (const float*)d_in[3];
    const float* rela_table = (const float*)d_in[4];
    const float* ent_table  = (const float*)d_in[5];
    const float* W1         = (const float*)d_in[6];
    const float* b1         = (const float*)d_in[7];
    const float* W2         = (const float*)d_in[8];
    const float* b2         = (const float*)d_in[9];
    const float* lin_W      = (const float*)d_in[10];
    const float* lin_b      = (const float*)d_in[11];
    const float* gamma      = (const float*)d_in[12];
    const float* beta       = (const float*)d_in[13];
    float* out = (float*)d_out;

    cudaFuncSetAttribute(k_drug, cudaFuncAttributeMaxDynamicSharedMemorySize, K1_SMEM_BYTES);

    k_b2sum<<<SNEI / 8, 256>>>(b2);
    k_drug<<<NDRUG, 256, K1_SMEM_BYTES>>>(dn, adjt, adjr, drug_table, rela_table,
                                          ent_table, W1, b1, W2);
    k_final<<<EDIM, 256>>>(dn, drug_table, lin_W, lin_b, gamma, beta, out);
}

// round 3
// speedup vs baseline: 1.1486x; 1.1486x over previous
#include <cuda_runtime.h>

#define NDRUG 846
#define EDIM  64
#define SNEI  1024
#define RLEN  100

// ---- scratch (__device__ globals: no allocation allowed) ----
__device__ float g_b2s[SNEI];           // row-sums of b2
__device__ float g_we[NDRUG * EDIM];    // weighted entity embedding per drug

// ------------------------------------------------------------------
// kernel 0: b2sum[s] = sum_f b2[s,f]
// ------------------------------------------------------------------
__global__ void k_b2sum(const float* __restrict__ b2) {
    int wid = threadIdx.x >> 5, lane = threadIdx.x & 31;
    int s = blockIdx.x * 8 + wid;
    if (s >= SNEI) return;
    float2 v = *reinterpret_cast<const float2*>(b2 + s * 64 + lane * 2);
    float acc = v.x + v.y;
    #pragma unroll
    for (int o = 16; o; o >>= 1) acc += __shfl_xor_sync(0xffffffffu, acc, o);
    if (lane == 0) g_b2s[s] = acc;
}

// ------------------------------------------------------------------
// kernel 1: one CTA per drug.
//   W1'[e,f] = drug_emb[e] * W1[n,e,f]               (folded at smem load)
//   M[r,f]   = sum_e rela_table[r,e] * W1'[e,f]      (smem GEMM, R from L1/L2)
//   w2sum[f] = sum_f' W2[n,f,f']
//   score[s] = dot(relu(M[r(s),:] + b1[s,:]), w2sum) + b2sum[s]
//   attn     = softmax_s(score)
//   we[n,f]  = sum_s attn[s] * ent_table[tail(s), f] (thresholded gather)
// ------------------------------------------------------------------
// smem layout (floats):
//   W1s    [0      , 4096 )
//   Ms     [4096   , 10496)
//   scores [10496  , 11520)
//   w2sum  [11520  , 11584)
//   psum   [11584  , 12096)
//   red    [12096  , 12128)
#define K1_SMEM_FLOATS 12128
#define K1_SMEM_BYTES  (K1_SMEM_FLOATS * 4)

__global__ void __launch_bounds__(256, 4)
k_drug(const int*   __restrict__ dn,
       const int*   __restrict__ adjt,
       const int*   __restrict__ adjr,
       const float* __restrict__ drug_table,
       const float* __restrict__ rela_table,
       const float* __restrict__ ent_table,
       const float* __restrict__ W1,
       const float* __restrict__ b1,
       const float* __restrict__ W2) {
    extern __shared__ float sm[];
    float* W1s    = sm;
    float* Ms     = sm + 4096;
    float* scores = sm + 10496;
    float* w2sum  = sm + 11520;
    float* psum   = sm + 11584;
    float* red    = sm + 12096;

    const int n    = blockIdx.x;
    const int tid  = threadIdx.x;
    const int wid  = tid >> 5;
    const int lane = tid & 31;

    const int dbase = dn[n] * 64;

    // W1' = diag(drug_emb) * W1  -> smem (row e scaled by d[e])
    {
        const float4* src = reinterpret_cast<const float4*>(W1 + (size_t)n * 4096);
        float4* dst = reinterpret_cast<float4*>(W1s);
        for (int i = tid; i < 1024; i += 256) {
            float4 w = src[i];
            float de = __ldg(drug_table + dbase + (i >> 4));
            w.x *= de; w.y *= de; w.z *= de; w.w *= de;
            dst[i] = w;
        }
    }

    // w2sum partials: thread (f = tid>>2, quarter q = tid&3) sums 16 contiguous
    {
        int f = tid >> 2, q = tid & 3;
        const float4* p = reinterpret_cast<const float4*>(W2 + (size_t)n * 4096 + f * 64 + q * 16);
        float4 a = p[0], b = p[1], c = p[2], d = p[3];
        psum[tid] = (a.x + a.y + a.z + a.w) + (b.x + b.y + b.z + b.w)
                  + (c.x + c.y + c.z + c.w) + (d.x + d.y + d.z + d.w);
    }
    __syncthreads();
    if (tid < 64)
        w2sum[tid] = psum[tid * 4] + psum[tid * 4 + 1] + psum[tid * 4 + 2] + psum[tid * 4 + 3];

    // ---- GEMM: M[r][f] = sum_e R[r][e] * W1'[e][f]; lane owns f = {2*lane, 2*lane+1}
    const float2* W1f2 = reinterpret_cast<const float2*>(W1s);
    const float4* R4 = reinterpret_cast<const float4*>(rela_table);   // [100][16]
    for (int r0 = wid * 4; r0 <= 96; r0 += 32) {
        float2 acc[4];
        #pragma unroll
        for (int j = 0; j < 4; j++) acc[j] = make_float2(0.f, 0.f);
        #pragma unroll 4
        for (int e0 = 0; e0 < 64; e0 += 4) {
            float a[4][4];
            #pragma unroll
            for (int j = 0; j < 4; j++)
                *reinterpret_cast<float4*>(a[j]) = __ldg(&R4[(r0 + j) * 16 + (e0 >> 2)]);
            #pragma unroll
            for (int ee = 0; ee < 4; ee++) {
                float2 w = W1f2[(e0 + ee) * 32 + lane];
                #pragma unroll
                for (int j = 0; j < 4; j++) {
                    acc[j].x = fmaf(a[j][ee], w.x, acc[j].x);
                    acc[j].y = fmaf(a[j][ee], w.y, acc[j].y);
                }
            }
        }
        #pragma unroll
        for (int j = 0; j < 4; j++)
            reinterpret_cast<float2*>(Ms)[(r0 + j) * 32 + lane] = acc[j];
    }
    __syncthreads();

    // ---- scores: 8-lane group per neighbor; 4 neighbors per warp-iteration.
    //   group g = lane>>3 owns s+g; lane covers features [sub*8, sub*8+8)
    const int g   = lane >> 3;
    const int sub = lane & 7;
    // loop-invariant w2sum slice -> registers
    const float4 w2a = *reinterpret_cast<const float4*>(&w2sum[sub * 8]);
    const float4 w2b = *reinterpret_cast<const float4*>(&w2sum[sub * 8 + 4]);
    const float4* Mf4  = reinterpret_cast<const float4*>(Ms);
    const float4* b1f4 = reinterpret_cast<const float4*>(b1);
    const int* adjr_n = adjr + (size_t)n * SNEI;
    #pragma unroll 2
    for (int sbase = wid * 4; sbase < SNEI; sbase += 32) {
        const int s = sbase + g;
        const int r = __ldg(adjr_n + s);
        float4 bv0 = __ldg(&b1f4[s * 16 + sub * 2]);
        float4 bv1 = __ldg(&b1f4[s * 16 + sub * 2 + 1]);
        float4 m0 = Mf4[r * 16 + sub * 2];
        float4 m1 = Mf4[r * 16 + sub * 2 + 1];
        float v;
        v  = fmaxf(m0.x + bv0.x, 0.f) * w2a.x;
        v  = fmaf(fmaxf(m0.y + bv0.y, 0.f), w2a.y, v);
        v  = fmaf(fmaxf(m0.z + bv0.z, 0.f), w2a.z, v);
        v  = fmaf(fmaxf(m0.w + bv0.w, 0.f), w2a.w, v);
        v  = fmaf(fmaxf(m1.x + bv1.x, 0.f), w2b.x, v);
        v  = fmaf(fmaxf(m1.y + bv1.y, 0.f), w2b.y, v);
        v  = fmaf(fmaxf(m1.z + bv1.z, 0.f), w2b.z, v);
        v  = fmaf(fmaxf(m1.w + bv1.w, 0.f), w2b.w, v);
        // reduce across the 8-lane group (xor of low 3 lane bits stays in group)
        v += __shfl_xor_sync(0xffffffffu, v, 4);
        v += __shfl_xor_sync(0xffffffffu, v, 2);
        v += __shfl_xor_sync(0xffffffffu, v, 1);
        if (sub == 0) scores[s] = v + g_b2s[s];
    }
    __syncthreads();

    // ---- softmax over 1024 scores (in smem)
    float lm = -1e30f;
    for (int i = tid; i < SNEI; i += 256) lm = fmaxf(lm, scores[i]);
    #pragma unroll
    for (int o = 16; o; o >>= 1) lm = fmaxf(lm, __shfl_xor_sync(0xffffffffu, lm, o));
    if (lane == 0) red[wid] = lm;
    __syncthreads();
    if (tid == 0) {
        float m = red[0];
        #pragma unroll
        for (int i = 1; i < 8; i++) m = fmaxf(m, red[i]);
        red[8] = m;
    }
    __syncthreads();
    const float mx = red[8];
    float ls = 0.f;
    for (int i = tid; i < SNEI; i += 256) {
        float w = __expf(scores[i] - mx);
        scores[i] = w;
        ls += w;
    }
    #pragma unroll
    for (int o = 16; o; o >>= 1) ls += __shfl_xor_sync(0xffffffffu, ls, o);
    if (lane == 0) red[16 + wid] = ls;
    __syncthreads();
    if (tid == 0) {
        float t = 0.f;
        #pragma unroll
        for (int i = 0; i < 8; i++) t += red[16 + i];
        red[9] = 1.f / t;
    }
    __syncthreads();
    const float inv = red[9];

    // ---- weighted entity gather (skip negligible attention weights)
    float2 acc = make_float2(0.f, 0.f);
    const float2* entf2 = reinterpret_cast<const float2*>(ent_table);
    const int* adjt_n = adjt + (size_t)n * SNEI;
    for (int s = wid; s < SNEI; s += 8) {
        float w = scores[s] * inv;           // uniform across warp
        if (w > 1e-8f) {
            int t = adjt_n[s];
            float2 ev = entf2[(size_t)t * 32 + lane];
            acc.x = fmaf(w, ev.x, acc.x);
            acc.y = fmaf(w, ev.y, acc.y);
        }
    }
    reinterpret_cast<float2*>(psum)[wid * 32 + lane] = acc;
    __syncthreads();
    if (tid < 64) {
        float v = 0.f;
        #pragma unroll
        for (int w = 0; w < 8; w++) v += psum[w * 64 + tid];
        g_we[n * 64 + tid] = v;
    }
}

// ------------------------------------------------------------------
// kernel 2: one CTA per output feature f.
// ------------------------------------------------------------------
__global__ void __launch_bounds__(256)
k_final(const int*   __restrict__ dn,
        const float* __restrict__ drug_table,
        const float* __restrict__ lin_W,
        const float* __restrict__ lin_b,
        const float* __restrict__ gamma,
        const float* __restrict__ beta,
        float* __restrict__ out) {
    __shared__ float lw[128];
    __shared__ float xcol[NDRUG];
    __shared__ float redbuf[16];
    __shared__ float s_mean, s_scale;

    const int f = blockIdx.x;
    const int tid = threadIdx.x, wid = tid >> 5, lane = tid & 31;

    if (tid < 128) lw[tid] = lin_W[f * 128 + tid];
    __syncthreads();

    const float lb = lin_b[f];
    float lsum = 0.f, lsq = 0.f;
    for (int n = wid; n < NDRUG; n += 8) {
        const float* we = g_we + n * 64;
        int db = dn[n] * 64;
        float v = we[lane] * lw[lane]
                + we[lane + 32] * lw[lane + 32]
                + drug_table[db + lane] * lw[64 + lane]
                + drug_table[db + lane + 32] * lw[96 + lane];
        #pragma unroll
        for (int o = 16; o; o >>= 1) v += __shfl_xor_sync(0xffffffffu, v, o);
        float x = fmaxf(v + lb, 0.f);
        if (lane == 0) { xcol[n] = x; lsum += x; lsq += x * x; }
    }
    if (lane == 0) { redbuf[wid] = lsum; redbuf[8 + wid] = lsq; }
    __syncthreads();
    if (tid == 0) {
        float sm = 0.f, sq = 0.f;
        #pragma unroll
        for (int i = 0; i < 8; i++) { sm += redbuf[i]; sq += redbuf[8 + i]; }
        float mean = sm / (float)NDRUG;
        float var  = sq / (float)NDRUG - mean * mean;
        s_mean  = mean;
        s_scale = rsqrtf(var + 1e-5f) * gamma[f];
    }
    __syncthreads();
    const float mean = s_mean, scal = s_scale, bet = beta[f];
    for (int n = tid; n < NDRUG; n += 256)
        out[n * 64 + f] = (xcol[n] - mean) * scal + bet;
}

// ------------------------------------------------------------------
extern "C" void kernel_launch(void* const* d_in, const int* in_sizes, int n_in,
                              void* d_out, int out_size) {
    const int*   dn         = (const int*)  d_in[0];
    const int*   adjt       = (const int*)  d_in[1];
    const int*   adjr       = (const int*)  d_in[2];
    const float* drug_table = (const float*)d_in[3];
    const float* rela_table = (const float*)d_in[4];
    const float* ent_table  = (const float*)d_in[5];
    const float* W1         = (const float*)d_in[6];
    const float* b1         = (const float*)d_in[7];
    const float* W2         = (const float*)d_in[8];
    const float* b2         = (const float*)d_in[9];
    const float* lin_W      = (const float*)d_in[10];
    const float* lin_b      = (const float*)d_in[11];
    const float* gamma      = (const float*)d_in[12];
    const float* beta       = (const float*)d_in[13];
    float* out = (float*)d_out;

    cudaFuncSetAttribute(k_drug, cudaFuncAttributeMaxDynamicSharedMemorySize, K1_SMEM_BYTES);

    k_b2sum<<<SNEI / 8, 256>>>(b2);
    k_drug<<<NDRUG, 256, K1_SMEM_BYTES>>>(dn, adjt, adjr, drug_table, rela_table,
                                          ent_table, W1, b1, W2);
    k_final<<<EDIM, 256>>>(dn, drug_table, lin_W, lin_b, gamma, beta, out);
}

// round 4
// speedup vs baseline: 1.1498x; 1.0011x over previous
#include <cuda_runtime.h>

#define NDRUG 846
#define EDIM  64
#define SNEI  1024
#define RLEN  100

// ---- scratch (__device__ globals: no allocation allowed) ----
__device__ float g_b2s[SNEI];           // row-sums of b2
__device__ float g_we[NDRUG * EDIM];    // weighted entity embedding per drug

// ------------------------------------------------------------------
// kernel 0: b2sum[s] = sum_f b2[s,f]
// ------------------------------------------------------------------
__global__ void k_b2sum(const float* __restrict__ b2) {
    int wid = threadIdx.x >> 5, lane = threadIdx.x & 31;
    int s = blockIdx.x * 8 + wid;
    if (s >= SNEI) return;
    float2 v = *reinterpret_cast<const float2*>(b2 + s * 64 + lane * 2);
    float acc = v.x + v.y;
    #pragma unroll
    for (int o = 16; o; o >>= 1) acc += __shfl_xor_sync(0xffffffffu, acc, o);
    if (lane == 0) g_b2s[s] = acc;
}

// ------------------------------------------------------------------
// kernel 1: one CTA per drug.
// smem layout (floats), with post-GEMM overlay onto the W1s region:
//   W1s    [0     , 4096 )   GEMM input
//     overlay after GEMM:
//       scores [0    , 1024)
//       cidx   [1024 , 2048)  (int)
//       psum2  [2048 , 2560)
//       red    [2560 , 2592)
//       cnt    [2592]         (int)
//   Ms     [4096  , 10496)
//   w2sum  [10496 , 10560)
//   psum0  [10560 , 10816)
#define K1_SMEM_FLOATS 10816
#define K1_SMEM_BYTES  (K1_SMEM_FLOATS * 4)

__global__ void __launch_bounds__(256, 5)
k_drug(const int*   __restrict__ dn,
       const int*   __restrict__ adjt,
       const int*   __restrict__ adjr,
       const float* __restrict__ drug_table,
       const float* __restrict__ rela_table,
       const float* __restrict__ ent_table,
       const float* __restrict__ W1,
       const float* __restrict__ b1,
       const float* __restrict__ W2) {
    extern __shared__ float sm[];
    float* W1s    = sm;
    float* Ms     = sm + 4096;
    float* w2sum  = sm + 10496;
    float* psum0  = sm + 10560;
    // post-GEMM overlay
    float* scores = sm;
    int*   cidx   = (int*)(sm + 1024);
    float* psum2  = sm + 2048;
    float* red    = sm + 2560;
    int*   cntp   = (int*)(sm + 2592);

    const int n    = blockIdx.x;
    const int tid  = threadIdx.x;
    const int wid  = tid >> 5;
    const int lane = tid & 31;

    const int dbase = dn[n] * 64;

    // W1' = diag(drug_emb) * W1  -> smem (row e scaled by d[e])
    {
        const float4* src = reinterpret_cast<const float4*>(W1 + (size_t)n * 4096);
        float4* dst = reinterpret_cast<float4*>(W1s);
        for (int i = tid; i < 1024; i += 256) {
            float4 w = src[i];
            float de = __ldg(drug_table + dbase + (i >> 4));
            w.x *= de; w.y *= de; w.z *= de; w.w *= de;
            dst[i] = w;
        }
    }

    // w2sum partials: thread (f = tid>>2, quarter q = tid&3) sums 16 contiguous
    {
        int f = tid >> 2, q = tid & 3;
        const float4* p = reinterpret_cast<const float4*>(W2 + (size_t)n * 4096 + f * 64 + q * 16);
        float4 a = p[0], b = p[1], c = p[2], d = p[3];
        psum0[tid] = (a.x + a.y + a.z + a.w) + (b.x + b.y + b.z + b.w)
                   + (c.x + c.y + c.z + c.w) + (d.x + d.y + d.z + d.w);
    }
    __syncthreads();
    if (tid < 64)
        w2sum[tid] = psum0[tid * 4] + psum0[tid * 4 + 1] + psum0[tid * 4 + 2] + psum0[tid * 4 + 3];

    // ---- GEMM: M[r][f] = sum_e R[r][e] * W1'[e][f]; lane owns f = {2*lane, 2*lane+1}
    const float2* W1f2 = reinterpret_cast<const float2*>(W1s);
    const float4* R4 = reinterpret_cast<const float4*>(rela_table);   // [100][16]
    for (int r0 = wid * 4; r0 <= 96; r0 += 32) {
        float2 acc[4];
        #pragma unroll
        for (int j = 0; j < 4; j++) acc[j] = make_float2(0.f, 0.f);
        #pragma unroll 4
        for (int e0 = 0; e0 < 64; e0 += 4) {
            float a[4][4];
            #pragma unroll
            for (int j = 0; j < 4; j++)
                *reinterpret_cast<float4*>(a[j]) = __ldg(&R4[(r0 + j) * 16 + (e0 >> 2)]);
            #pragma unroll
            for (int ee = 0; ee < 4; ee++) {
                float2 w = W1f2[(e0 + ee) * 32 + lane];
                #pragma unroll
                for (int j = 0; j < 4; j++) {
                    acc[j].x = fmaf(a[j][ee], w.x, acc[j].x);
                    acc[j].y = fmaf(a[j][ee], w.y, acc[j].y);
                }
            }
        }
        #pragma unroll
        for (int j = 0; j < 4; j++)
            reinterpret_cast<float2*>(Ms)[(r0 + j) * 32 + lane] = acc[j];
    }
    __syncthreads();   // GEMM done: W1s region is now dead -> overlay live

    // ---- scores: 8-lane group per neighbor; 8 neighbors per unrolled iteration.
    const int g   = lane >> 3;
    const int sub = lane & 7;
    const float4 w2a = *reinterpret_cast<const float4*>(&w2sum[sub * 8]);
    const float4 w2b = *reinterpret_cast<const float4*>(&w2sum[sub * 8 + 4]);
    const float4* Mf4  = reinterpret_cast<const float4*>(Ms);
    const float4* b1f4 = reinterpret_cast<const float4*>(b1);
    const int* adjr_n = adjr + (size_t)n * SNEI;
    for (int sbase = wid * 4; sbase < SNEI; sbase += 64) {
        const int sA = sbase + g;
        const int sB = sbase + 32 + g;
        // issue all global loads up front (6 LDGs in flight)
        const int rA = __ldg(adjr_n + sA);
        const int rB = __ldg(adjr_n + sB);
        float4 bA0 = __ldg(&b1f4[sA * 16 + sub * 2]);
        float4 bA1 = __ldg(&b1f4[sA * 16 + sub * 2 + 1]);
        float4 bB0 = __ldg(&b1f4[sB * 16 + sub * 2]);
        float4 bB1 = __ldg(&b1f4[sB * 16 + sub * 2 + 1]);
        float4 mA0 = Mf4[rA * 16 + sub * 2];
        float4 mA1 = Mf4[rA * 16 + sub * 2 + 1];
        float4 mB0 = Mf4[rB * 16 + sub * 2];
        float4 mB1 = Mf4[rB * 16 + sub * 2 + 1];

        float vA, vB;
        vA  = fmaxf(mA0.x + bA0.x, 0.f) * w2a.x;
        vA  = fmaf(fmaxf(mA0.y + bA0.y, 0.f), w2a.y, vA);
        vA  = fmaf(fmaxf(mA0.z + bA0.z, 0.f), w2a.z, vA);
        vA  = fmaf(fmaxf(mA0.w + bA0.w, 0.f), w2a.w, vA);
        vA  = fmaf(fmaxf(mA1.x + bA1.x, 0.f), w2b.x, vA);
        vA  = fmaf(fmaxf(mA1.y + bA1.y, 0.f), w2b.y, vA);
        vA  = fmaf(fmaxf(mA1.z + bA1.z, 0.f), w2b.z, vA);
        vA  = fmaf(fmaxf(mA1.w + bA1.w, 0.f), w2b.w, vA);
        vB  = fmaxf(mB0.x + bB0.x, 0.f) * w2a.x;
        vB  = fmaf(fmaxf(mB0.y + bB0.y, 0.f), w2a.y, vB);
        vB  = fmaf(fmaxf(mB0.z + bB0.z, 0.f), w2a.z, vB);
        vB  = fmaf(fmaxf(mB0.w + bB0.w, 0.f), w2a.w, vB);
        vB  = fmaf(fmaxf(mB1.x + bB1.x, 0.f), w2b.x, vB);
        vB  = fmaf(fmaxf(mB1.y + bB1.y, 0.f), w2b.y, vB);
        vB  = fmaf(fmaxf(mB1.z + bB1.z, 0.f), w2b.z, vB);
        vB  = fmaf(fmaxf(mB1.w + bB1.w, 0.f), w2b.w, vB);
        // reduce across the 8-lane group
        vA += __shfl_xor_sync(0xffffffffu, vA, 4);
        vB += __shfl_xor_sync(0xffffffffu, vB, 4);
        vA += __shfl_xor_sync(0xffffffffu, vA, 2);
        vB += __shfl_xor_sync(0xffffffffu, vB, 2);
        vA += __shfl_xor_sync(0xffffffffu, vA, 1);
        vB += __shfl_xor_sync(0xffffffffu, vB, 1);
        if (sub == 0) {
            scores[sA] = vA + g_b2s[sA];
            scores[sB] = vB + g_b2s[sB];
        }
    }
    __syncthreads();

    // ---- softmax over 1024 scores (in smem)
    float lm = -1e30f;
    for (int i = tid; i < SNEI; i += 256) lm = fmaxf(lm, scores[i]);
    #pragma unroll
    for (int o = 16; o; o >>= 1) lm = fmaxf(lm, __shfl_xor_sync(0xffffffffu, lm, o));
    if (lane == 0) red[wid] = lm;
    __syncthreads();
    if (tid == 0) {
        float m = red[0];
        #pragma unroll
        for (int i = 1; i < 8; i++) m = fmaxf(m, red[i]);
        red[8] = m;
        *cntp = 0;
    }
    __syncthreads();
    const float mx = red[8];
    float ls = 0.f;
    for (int i = tid; i < SNEI; i += 256) {
        float w = __expf(scores[i] - mx);
        scores[i] = w;
        ls += w;
    }
    #pragma unroll
    for (int o = 16; o; o >>= 1) ls += __shfl_xor_sync(0xffffffffu, ls, o);
    if (lane == 0) red[16 + wid] = ls;
    __syncthreads();
    if (tid == 0) {
        float t = 0.f;
        #pragma unroll
        for (int i = 0; i < 8; i++) t += red[16 + i];
        red[9] = 1.f / t;
    }
    __syncthreads();
    const float inv = red[9];

    // ---- compact surviving neighbors (w > 1e-8), then gather only those
    for (int i = tid; i < SNEI; i += 256) {
        if (scores[i] * inv > 1e-8f) {
            int p = atomicAdd(cntp, 1);
            cidx[p] = i;
        }
    }
    __syncthreads();
    const int C = *cntp;

    float2 acc = make_float2(0.f, 0.f);
    const float2* entf2 = reinterpret_cast<const float2*>(ent_table);
    const int* adjt_n = adjt + (size_t)n * SNEI;
    for (int j = wid; j < C; j += 8) {
        int s = cidx[j];
        float w = scores[s] * inv;           // uniform across warp
        int t = __ldg(adjt_n + s);
        float2 ev = entf2[(size_t)t * 32 + lane];
        acc.x = fmaf(w, ev.x, acc.x);
        acc.y = fmaf(w, ev.y, acc.y);
    }
    reinterpret_cast<float2*>(psum2)[wid * 32 + lane] = acc;
    __syncthreads();
    if (tid < 64) {
        float v = 0.f;
        #pragma unroll
        for (int w = 0; w < 8; w++) v += psum2[w * 64 + tid];
        g_we[n * 64 + tid] = v;
    }
}

// ------------------------------------------------------------------
// kernel 2: one CTA per output feature f.
// ------------------------------------------------------------------
__global__ void __launch_bounds__(256)
k_final(const int*   __restrict__ dn,
        const float* __restrict__ drug_table,
        const float* __restrict__ lin_W,
        const float* __restrict__ lin_b,
        const float* __restrict__ gamma,
        const float* __restrict__ beta,
        float* __restrict__ out) {
    __shared__ float lw[128];
    __shared__ float xcol[NDRUG];
    __shared__ float redbuf[16];
    __shared__ float s_mean, s_scale;

    const int f = blockIdx.x;
    const int tid = threadIdx.x, wid = tid >> 5, lane = tid & 31;

    if (tid < 128) lw[tid] = lin_W[f * 128 + tid];
    __syncthreads();

    const float lb = lin_b[f];
    float lsum = 0.f, lsq = 0.f;
    for (int n = wid; n < NDRUG; n += 8) {
        const float* we = g_we + n * 64;
        int db = dn[n] * 64;
        float v = we[lane] * lw[lane]
                + we[lane + 32] * lw[lane + 32]
                + drug_table[db + lane] * lw[64 + lane]
                + drug_table[db + lane + 32] * lw[96 + lane];
        #pragma unroll
        for (int o = 16; o; o >>= 1) v += __shfl_xor_sync(0xffffffffu, v, o);
        float x = fmaxf(v + lb, 0.f);
        if (lane == 0) { xcol[n] = x; lsum += x; lsq += x * x; }
    }
    if (lane == 0) { redbuf[wid] = lsum; redbuf[8 + wid] = lsq; }
    __syncthreads();
    if (tid == 0) {
        float sm = 0.f, sq = 0.f;
        #pragma unroll
        for (int i = 0; i < 8; i++) { sm += redbuf[i]; sq += redbuf[8 + i]; }
        float mean = sm / (float)NDRUG;
        float var  = sq / (float)NDRUG - mean * mean;
        s_mean  = mean;
        s_scale = rsqrtf(var + 1e-5f) * gamma[f];
    }
    __syncthreads();
    const float mean = s_mean, scal = s_scale, bet = beta[f];
    for (int n = tid; n < NDRUG; n += 256)
        out[n * 64 + f] = (xcol[n] - mean) * scal + bet;
}

// ------------------------------------------------------------------
extern "C" void kernel_launch(void* const* d_in, const int* in_sizes, int n_in,
                              void* d_out, int out_size) {
    const int*   dn         = (const int*)  d_in[0];
    const int*   adjt       = (const int*)  d_in[1];
    const int*   adjr       = (const int*)  d_in[2];
    const float* drug_table = (const float*)d_in[3];
    const float* rela_table = (const float*)d_in[4];
    const float* ent_table  = (const float*)d_in[5];
    const float* W1         = (const float*)d_in[6];
    const float* b1         = (const float*)d_in[7];
    const float* W2         = (const float*)d_in[8];
    const float* b2         = (const float*)d_in[9];
    const float* lin_W      = (const float*)d_in[10];
    const float* lin_b      = (const float*)d_in[11];
    const float* gamma      = (const float*)d_in[12];
    const float* beta       = (const float*)d_in[13];
    float* out = (float*)d_out;

    cudaFuncSetAttribute(k_drug, cudaFuncAttributeMaxDynamicSharedMemorySize, K1_SMEM_BYTES);

    k_b2sum<<<SNEI / 8, 256>>>(b2);
    k_drug<<<NDRUG, 256, K1_SMEM_BYTES>>>(dn, adjt, adjr, drug_table, rela_table,
                                          ent_table, W1, b1, W2);
    k_final<<<EDIM, 256>>>(dn, drug_table, lin_W, lin_b, gamma, beta, out);
}